// round 15
// baseline (speedup 1.0000x reference)
#include <cuda_runtime.h>
#include <cuda_bf16.h>
#include <cstdint>

// Problem constants
#define B_  2
#define S_  4096
#define D_  768
#define H_  12
#define HD_ 64
#define W_  256
#define NC_ 16
#define G_  32
#define SCALE_ 0.125f

#define BHSD (B_*H_*S_*HD_)   // 6291456
#define NSPLITG 32            // gattn split-K partials (8 sp x 4 kw)

// ---------------------------------------------------------------------------
__device__ __forceinline__ uint32_t smem_u32(const void* p) {
    uint32_t a;
    asm("{ .reg .u64 t; cvta.to.shared.u64 t, %1; cvt.u32.u64 %0, t; }" : "=r"(a) : "l"(p));
    return a;
}
#define CPA16(sa, g) asm volatile("cp.async.cg.shared.global [%0], [%1], 16;" :: "r"(sa), "l"(g))
#define CPA_COMMIT() asm volatile("cp.async.commit_group;" ::: "memory")
#define CPA_WAIT1()  asm volatile("cp.async.wait_group 1;" ::: "memory")
#define CPA_WAIT0()  asm volatile("cp.async.wait_group 0;" ::: "memory")
#define LDM4(r, addr) \
  asm volatile("ldmatrix.sync.aligned.m8n8.x4.shared.b16 {%0,%1,%2,%3}, [%4];" \
    : "=r"((r)[0]), "=r"((r)[1]), "=r"((r)[2]), "=r"((r)[3]) : "r"(addr))
#define LDM4T(r, addr) \
  asm volatile("ldmatrix.sync.aligned.m8n8.x4.trans.shared.b16 {%0,%1,%2,%3}, [%4];" \
    : "=r"((r)[0]), "=r"((r)[1]), "=r"((r)[2]), "=r"((r)[3]) : "r"(addr))
#define MMA16816(d, a, b0, b1) \
  asm volatile("mma.sync.aligned.m16n8k16.row.col.f32.bf16.bf16.f32 " \
    "{%0,%1,%2,%3}, {%4,%5,%6,%7}, {%8,%9}, {%0,%1,%2,%3};" \
    : "+f"((d)[0]), "+f"((d)[1]), "+f"((d)[2]), "+f"((d)[3]) \
    : "r"((a)[0]), "r"((a)[1]), "r"((a)[2]), "r"((a)[3]), "r"(b0), "r"(b1))

// 64B-row swizzle: seg' = seg ^ ((row>>1)&3)  (conflict-free for ldmatrix + cp.async)
#define SWZ64(row, seg) ((uint32_t)((row) * 64 + ((((seg) ^ ((row) >> 1)) & 3) * 16)))

// ---------------------------------------------------------------------------
// Device scratch (bf16 hi/lo everywhere the tensor cores touch)
__device__ __nv_bfloat16 d_Qhi[BHSD], d_Qlo[BHSD];
__device__ __nv_bfloat16 d_Khi[BHSD], d_Klo[BHSD];
__device__ __nv_bfloat16 d_Vhi[BHSD], d_Vlo[BHSD];
__device__ __nv_bfloat16 d_Kghi[BHSD], d_Kglo[BHSD];
__device__ __nv_bfloat16 d_Vghi[BHSD], d_Vglo[BHSD];
__device__ __nv_bfloat16 d_qghi[B_*H_*G_*HD_], d_qglo[B_*H_*G_*HD_];
__device__ __nv_bfloat16 d_Ahi[B_*S_*D_];
__device__ __nv_bfloat16 d_Alo[B_*S_*D_];
__device__ __nv_bfloat16 d_Whi[6][D_*D_];   // transposed [n][k]
__device__ __nv_bfloat16 d_Wlo[6][D_*D_];
__device__ float d_lpart[B_*H_*NSPLITG*G_];
__device__ float d_accpart[B_*H_*NSPLITG*G_*HD_];

// ---------------------------------------------------------------------------
// Prepass: hidden -> bf16 hi/lo
__global__ __launch_bounds__(256) void convA_kernel(const float* __restrict__ A)
{
    int i = (blockIdx.x * 256 + threadIdx.x) * 4;
    float4 a = *(const float4*)&A[i];
    float av[4] = {a.x, a.y, a.z, a.w};
    __nv_bfloat16 h[4], l[4];
    #pragma unroll
    for (int j = 0; j < 4; j++) {
        h[j] = __float2bfloat16(av[j]);
        l[j] = __float2bfloat16(av[j] - __bfloat162float(h[j]));
    }
    *(uint2*)&d_Ahi[i] = *(uint2*)h;
    *(uint2*)&d_Alo[i] = *(uint2*)l;
}

// Prepass (fused over 6 weights): W[k][n] -> Wt_hi/lo[n][k] bf16
__global__ __launch_bounds__(256) void convW_kernel(
    const float* __restrict__ W0, const float* __restrict__ W1,
    const float* __restrict__ W2, const float* __restrict__ W3,
    const float* __restrict__ W4, const float* __restrict__ W5)
{
    __shared__ float t[32][33];
    const int which = blockIdx.z;
    const float* __restrict__ W = (which == 0) ? W0 : (which == 1) ? W1
                                : (which == 2) ? W2 : (which == 3) ? W3
                                : (which == 4) ? W4 : W5;
    const int n0 = blockIdx.x * 32, k0 = blockIdx.y * 32;
    const int tx = threadIdx.x, ty = threadIdx.y;   // (32, 8)
    #pragma unroll
    for (int r = 0; r < 32; r += 8)
        t[ty + r][tx] = W[(k0 + ty + r) * D_ + n0 + tx];
    __syncthreads();
    #pragma unroll
    for (int r = 0; r < 32; r += 8) {
        float v = t[tx][ty + r];
        __nv_bfloat16 hh = __float2bfloat16(v);
        __nv_bfloat16 ll = __float2bfloat16(v - __bfloat162float(hh));
        d_Whi[which][(n0 + ty + r) * D_ + k0 + tx] = hh;
        d_Wlo[which][(n0 + ty + r) * D_ + k0 + tx] = ll;
    }
}

// ---------------------------------------------------------------------------
// Fused projection GEMMs on mma.sync, hi/lo 3-term, 3-stage cp.async pipeline,
// swizzled 64B smem rows, ONE barrier per K-chunk.
// grid = (6, 64, 3), which = blockIdx.z + zoff. which==5 only y==0/32.
// ---------------------------------------------------------------------------
#define GTILE 8192                 // 128 rows x 64B, swizzled
#define GSTAGE (4 * GTILE)         // 4 operands per stage
#define GEMM_DYN (3 * GSTAGE)      // 98304

__global__ __launch_bounds__(256, 2) void gemm_kernel(
    const float* __restrict__ bq,  const float* __restrict__ bk,
    const float* __restrict__ bv,  const float* __restrict__ bkg,
    const float* __restrict__ bvg, const float* __restrict__ bqg,
    int zoff)
{
    const int which = blockIdx.z + zoff;
    if (which == 5 && blockIdx.y != 0 && blockIdx.y != 32) return;
    extern __shared__ char smraw[];
    const uint32_t sb = smem_u32(smraw);
    const int tid = threadIdx.x, wid = tid >> 5, lane = tid & 31;
    const int mw = wid & 3, nw = wid >> 2;
    const int n0 = blockIdx.x * 128;
    const int m0 = blockIdx.y * 128;
    const float* bias = (which == 0) ? bq : (which == 1) ? bk : (which == 2) ? bv
                       : (which == 3) ? bkg : (which == 4) ? bvg : bqg;
    const __nv_bfloat16* __restrict__ Ahi = d_Ahi;
    const __nv_bfloat16* __restrict__ Alo = d_Alo;
    const __nv_bfloat16* __restrict__ Whi = d_Whi[which];
    const __nv_bfloat16* __restrict__ Wlo = d_Wlo[which];

    float acc[2][8][4];
    #pragma unroll
    for (int mt = 0; mt < 2; mt++)
        #pragma unroll
        for (int nt = 0; nt < 8; nt++)
            #pragma unroll
            for (int r = 0; r < 4; r++) acc[mt][nt][r] = 0.f;

    const int lrow = tid >> 2, lch = tid & 3;     // 64 rows x 4 segs
    const int lrow2 = lrow + 64;
    const uint32_t o1 = SWZ64(lrow, lch), o2 = SWZ64(lrow2, lch);

    auto load_chunk = [&](int buf, int k0) {
        uint32_t base = sb + buf * GSTAGE;
        CPA16(base + o1, &Ahi[(m0 + lrow) * D_ + k0 + lch * 8]);
        CPA16(base + o2, &Ahi[(m0 + lrow2) * D_ + k0 + lch * 8]);
        base += GTILE;
        CPA16(base + o1, &Alo[(m0 + lrow) * D_ + k0 + lch * 8]);
        CPA16(base + o2, &Alo[(m0 + lrow2) * D_ + k0 + lch * 8]);
        base += GTILE;
        CPA16(base + o1, &Whi[(n0 + lrow) * D_ + k0 + lch * 8]);
        CPA16(base + o2, &Whi[(n0 + lrow2) * D_ + k0 + lch * 8]);
        base += GTILE;
        CPA16(base + o1, &Wlo[(n0 + lrow) * D_ + k0 + lch * 8]);
        CPA16(base + o2, &Wlo[(n0 + lrow2) * D_ + k0 + lch * 8]);
        CPA_COMMIT();
    };

    load_chunk(0, 0);
    load_chunk(1, 32);

    int cur = 0;
    #pragma unroll 1
    for (int c = 0; c < 24; c++) {
        if (c == 23) CPA_WAIT0(); else CPA_WAIT1();
        __syncthreads();
        if (c + 2 < 24) {
            int nxt = cur + 2; if (nxt >= 3) nxt -= 3;
            load_chunk(nxt, (c + 2) * 32);
        }

        const uint32_t aBase  = sb + cur * GSTAGE;
        const uint32_t alBase = aBase + GTILE;
        const uint32_t bBase  = aBase + 2 * GTILE;
        const uint32_t blBase = aBase + 3 * GTILE;

        #pragma unroll
        for (int ks = 0; ks < 2; ks++) {
            uint32_t ahi[2][4], alo[2][4];
            const int aseg = ks * 2 + ((lane >> 4) & 1);
            #pragma unroll
            for (int mt = 0; mt < 2; mt++) {
                int row = mw * 32 + mt * 16 + (lane & 15);
                LDM4(ahi[mt], aBase + SWZ64(row, aseg));
                LDM4(alo[mt], alBase + SWZ64(row, aseg));
            }
            const int bseg = ks * 2 + ((lane >> 3) & 1);
            #pragma unroll
            for (int nh = 0; nh < 2; nh++) {
                uint32_t bhi[2][4], blo[2][4];
                #pragma unroll
                for (int q = 0; q < 2; q++) {
                    int row = nw * 64 + nh * 32 + q * 16 + (lane & 7) + ((lane >> 4) << 3);
                    LDM4(bhi[q], bBase + SWZ64(row, bseg));
                    LDM4(blo[q], blBase + SWZ64(row, bseg));
                }
                #pragma unroll
                for (int mt = 0; mt < 2; mt++)
                    #pragma unroll
                    for (int q = 0; q < 2; q++)
                        #pragma unroll
                        for (int p = 0; p < 2; p++) {
                            int nt = nh * 4 + q * 2 + p;
                            MMA16816(acc[mt][nt], ahi[mt], bhi[q][p*2], bhi[q][p*2+1]);
                            MMA16816(acc[mt][nt], ahi[mt], blo[q][p*2], blo[q][p*2+1]);
                            MMA16816(acc[mt][nt], alo[mt], bhi[q][p*2], bhi[q][p*2+1]);
                        }
            }
        }
        cur++; if (cur >= 3) cur -= 3;
    }

    // Epilogue: bf16 hi/lo split stores
    const int g = lane >> 2, tg = lane & 3;
    #pragma unroll
    for (int mt = 0; mt < 2; mt++)
        #pragma unroll
        for (int half = 0; half < 2; half++) {
            int m = m0 + mw * 32 + mt * 16 + g + half * 8;
            int b = m >> 12, s = m & 4095;
            #pragma unroll
            for (int nt = 0; nt < 8; nt++) {
                int n = n0 + nw * 64 + nt * 8 + tg * 2;
                float v0 = acc[mt][nt][half * 2 + 0] + bias[n];
                float v1 = acc[mt][nt][half * 2 + 1] + bias[n + 1];
                int h = n >> 6, hd = n & 63;
                if (which == 0 || which == 5) { v0 *= SCALE_; v1 *= SCALE_; }
                if (which == 5 && s >= G_) continue;
                __nv_bfloat16 h0 = __float2bfloat16(v0);
                __nv_bfloat16 h1 = __float2bfloat16(v1);
                __nv_bfloat16 l0 = __float2bfloat16(v0 - __bfloat162float(h0));
                __nv_bfloat16 l1 = __float2bfloat16(v1 - __bfloat162float(h1));
                __nv_bfloat162 hp; hp.x = h0; hp.y = h1;
                __nv_bfloat162 lp; lp.x = l0; lp.y = l1;
                size_t bidx = ((size_t)(b * H_ + h) * S_ + s) * HD_ + hd;
                switch (which) {
                    case 0:
                        *(__nv_bfloat162*)&d_Qhi[bidx] = hp;
                        *(__nv_bfloat162*)&d_Qlo[bidx] = lp; break;
                    case 1:
                        *(__nv_bfloat162*)&d_Khi[bidx] = hp;
                        *(__nv_bfloat162*)&d_Klo[bidx] = lp; break;
                    case 2:
                        *(__nv_bfloat162*)&d_Vhi[bidx] = hp;
                        *(__nv_bfloat162*)&d_Vlo[bidx] = lp; break;
                    case 3:
                        *(__nv_bfloat162*)&d_Kghi[bidx] = hp;
                        *(__nv_bfloat162*)&d_Kglo[bidx] = lp; break;
                    case 4:
                        *(__nv_bfloat162*)&d_Vghi[bidx] = hp;
                        *(__nv_bfloat162*)&d_Vglo[bidx] = lp; break;
                    default: {
                        size_t qidx = ((size_t)(b * H_ + h) * G_ + s) * HD_ + hd;
                        *(__nv_bfloat162*)&d_qghi[qidx] = hp;
                        *(__nv_bfloat162*)&d_qglo[qidx] = lp; break;
                    }
                }
            }
        }
}

// ---------------------------------------------------------------------------
// Global attention on mma.sync (unchanged; 21 us).
// ---------------------------------------------------------------------------
__global__ __launch_bounds__(256, 2) void gattn_mma_kernel()
{
    __shared__ __align__(16) char kh_sm[16384];
    __shared__ __align__(16) char kl_sm[16384];
    __shared__ __align__(16) char vh_sm[16384];
    __shared__ __align__(16) char vl_sm[16384];
    const uint32_t sKhi = smem_u32(kh_sm), sKlo = smem_u32(kl_sm);
    const uint32_t sVhi = smem_u32(vh_sm), sVlo = smem_u32(vl_sm);
    const int tid = threadIdx.x, wid = tid >> 5, lane = tid & 31;
    const int sp = blockIdx.x, h = blockIdx.y, b = blockIdx.z;
    const int bh = b * H_ + h;
    const int mw = wid & 1, kw = wid >> 1;
    const int g = lane >> 2, tg = lane & 3;

    uint32_t qhi[4][4], qlo[4][4];
    {
        const __nv_bfloat16* Qh = &d_qghi[((size_t)bh * G_ + mw * 16) * 64];
        const __nv_bfloat16* Ql = &d_qglo[((size_t)bh * G_ + mw * 16) * 64];
        #pragma unroll
        for (int ks = 0; ks < 4; ks++) {
            int c0 = ks * 16 + tg * 2;
            qhi[ks][0] = *(const uint32_t*)&Qh[g * 64 + c0];
            qhi[ks][1] = *(const uint32_t*)&Qh[(g + 8) * 64 + c0];
            qhi[ks][2] = *(const uint32_t*)&Qh[g * 64 + c0 + 8];
            qhi[ks][3] = *(const uint32_t*)&Qh[(g + 8) * 64 + c0 + 8];
            qlo[ks][0] = *(const uint32_t*)&Ql[g * 64 + c0];
            qlo[ks][1] = *(const uint32_t*)&Ql[(g + 8) * 64 + c0];
            qlo[ks][2] = *(const uint32_t*)&Ql[g * 64 + c0 + 8];
            qlo[ks][3] = *(const uint32_t*)&Ql[(g + 8) * 64 + c0 + 8];
        }
    }

    float oacc[8][4];
    #pragma unroll
    for (int i = 0; i < 8; i++)
        #pragma unroll
        for (int r = 0; r < 4; r++) oacc[i][r] = 0.f;
    float lsum0 = 0.f, lsum1 = 0.f;

    #pragma unroll 1
    for (int ch = 0; ch < 4; ch++) {
        __syncthreads();
        #pragma unroll
        for (int r = 0; r < 4; r++) {
            int idx = tid + r * 256;
            int row = idx >> 3, seg = idx & 7;
            uint32_t off = row * 128 + ((seg ^ (row & 7)) * 16);
            size_t src = ((size_t)bh * S_ + sp * 512 + ch * 128 + row) * 64 + seg * 8;
            CPA16(sKhi + off, &d_Kghi[src]);
            CPA16(sKlo + off, &d_Kglo[src]);
            CPA16(sVhi + off, &d_Vghi[src]);
            CPA16(sVlo + off, &d_Vglo[src]);
        }
        CPA_COMMIT(); CPA_WAIT0();
        __syncthreads();

        const int kb = kw * 32;
        float sc[4][4];
        #pragma unroll
        for (int i = 0; i < 4; i++)
            #pragma unroll
            for (int r = 0; r < 4; r++) sc[i][r] = 0.f;

        #pragma unroll
        for (int ks = 0; ks < 4; ks++) {
            uint32_t kh[2][4], kl[2][4];
            #pragma unroll
            for (int q2 = 0; q2 < 2; q2++) {
                int row = kb + q2 * 16 + (lane & 7) + ((lane >> 4) << 3);
                int seg = ks * 2 + ((lane >> 3) & 1);
                uint32_t addr = row * 128 + ((seg ^ (row & 7)) * 16);
                LDM4(kh[q2], sKhi + addr);
                LDM4(kl[q2], sKlo + addr);
            }
            #pragma unroll
            for (int q2 = 0; q2 < 2; q2++)
                #pragma unroll
                for (int p = 0; p < 2; p++) {
                    int nt = q2 * 2 + p;
                    MMA16816(sc[nt], qhi[ks], kh[q2][p*2], kh[q2][p*2+1]);
                    MMA16816(sc[nt], qhi[ks], kl[q2][p*2], kl[q2][p*2+1]);
                    MMA16816(sc[nt], qlo[ks], kh[q2][p*2], kh[q2][p*2+1]);
                }
        }

        uint32_t pah[2][4], pal[2][4];
        #pragma unroll
        for (int nt = 0; nt < 4; nt++) {
            float p00 = __expf(sc[nt][0]), p01 = __expf(sc[nt][1]);
            float p10 = __expf(sc[nt][2]), p11 = __expf(sc[nt][3]);
            lsum0 += p00 + p01;
            lsum1 += p10 + p11;
            __nv_bfloat16 h00 = __float2bfloat16(p00);
            __nv_bfloat16 h01 = __float2bfloat16(p01);
            __nv_bfloat16 h10 = __float2bfloat16(p10);
            __nv_bfloat16 h11 = __float2bfloat16(p11);
            __nv_bfloat162 hp0; hp0.x = h00; hp0.y = h01;
            __nv_bfloat162 hp1; hp1.x = h10; hp1.y = h11;
            __nv_bfloat162 lp0;
            lp0.x = __float2bfloat16(p00 - __bfloat162float(h00));
            lp0.y = __float2bfloat16(p01 - __bfloat162float(h01));
            __nv_bfloat162 lp1;
            lp1.x = __float2bfloat16(p10 - __bfloat162float(h10));
            lp1.y = __float2bfloat16(p11 - __bfloat162float(h11));
            pah[nt >> 1][(nt & 1) * 2 + 0] = *(uint32_t*)&hp0;
            pah[nt >> 1][(nt & 1) * 2 + 1] = *(uint32_t*)&hp1;
            pal[nt >> 1][(nt & 1) * 2 + 0] = *(uint32_t*)&lp0;
            pal[nt >> 1][(nt & 1) * 2 + 1] = *(uint32_t*)&lp1;
        }

        #pragma unroll
        for (int ksp = 0; ksp < 2; ksp++) {
            #pragma unroll
            for (int dg = 0; dg < 4; dg++) {
                uint32_t vh[4], vl[4];
                int row = kb + ksp * 16 + (lane & 15);
                int seg = dg * 2 + (lane >> 4);
                uint32_t addr = row * 128 + ((seg ^ (row & 7)) * 16);
                LDM4T(vh, sVhi + addr);
                LDM4T(vl, sVlo + addr);
                MMA16816(oacc[dg * 2 + 0], pah[ksp], vh[0], vh[1]);
                MMA16816(oacc[dg * 2 + 0], pal[ksp], vh[0], vh[1]);
                MMA16816(oacc[dg * 2 + 0], pah[ksp], vl[0], vl[1]);
                MMA16816(oacc[dg * 2 + 1], pah[ksp], vh[2], vh[3]);
                MMA16816(oacc[dg * 2 + 1], pal[ksp], vh[2], vh[3]);
                MMA16816(oacc[dg * 2 + 1], pah[ksp], vl[2], vl[3]);
            }
        }
    }

    lsum0 += __shfl_xor_sync(0xffffffffu, lsum0, 1);
    lsum0 += __shfl_xor_sync(0xffffffffu, lsum0, 2);
    lsum1 += __shfl_xor_sync(0xffffffffu, lsum1, 1);
    lsum1 += __shfl_xor_sync(0xffffffffu, lsum1, 2);
    const int part = sp * 4 + kw;
    const int r0 = mw * 16 + g, r1 = r0 + 8;
    if (tg == 0) {
        d_lpart[((size_t)bh * NSPLITG + part) * G_ + r0] = lsum0;
        d_lpart[((size_t)bh * NSPLITG + part) * G_ + r1] = lsum1;
    }
    float* a0 = &d_accpart[(((size_t)bh * NSPLITG + part) * G_ + r0) * HD_];
    float* a1 = &d_accpart[(((size_t)bh * NSPLITG + part) * G_ + r1) * HD_];
    #pragma unroll
    for (int nt = 0; nt < 8; nt++) {
        float2 w0; w0.x = oacc[nt][0]; w0.y = oacc[nt][1];
        float2 w1; w1.x = oacc[nt][2]; w1.y = oacc[nt][3];
        *(float2*)&a0[nt * 8 + tg * 2] = w0;
        *(float2*)&a1[nt * 8 + tg * 2] = w1;
    }
}

__global__ __launch_bounds__(64) void gattn_combine_kernel(float* __restrict__ out)
{
    const int idx = blockIdx.x;
    const int bh = idx >> 5;
    const int g = idx & 31;
    const int b = bh / H_, h = bh % H_;
    const int d = threadIdx.x;
    float l = 0.f, a = 0.f;
    #pragma unroll
    for (int sp = 0; sp < NSPLITG; sp++) {
        l += d_lpart[((size_t)bh * NSPLITG + sp) * G_ + g];
        a += d_accpart[(((size_t)bh * NSPLITG + sp) * G_ + g) * HD_ + d];
    }
    out[(b * S_ + g) * D_ + h * HD_ + d] = a / l;
}

// ---------------------------------------------------------------------------
// Band + global-key attention: 3-stage cp.async pipeline, one barrier/tile,
// warp-uniform SKIP of fully-masked segments, unmasked fast path, hoisted
// per-thread mask bounds.
// ---------------------------------------------------------------------------
#define BTILE 8192
#define BSTAGE (4 * BTILE)
#define BAND_DYN (3 * BSTAGE)     // 98304

__global__ __launch_bounds__(256, 2) void band_mma_kernel(float* __restrict__ out)
{
    extern __shared__ char bsm[];
    const uint32_t sb = smem_u32(bsm);
    const int tid = threadIdx.x, wid = tid >> 5, lane = tid & 31;
    const int c = blockIdx.x >> 1, qh = blockIdx.x & 1;
    const int h = blockIdx.y, b = blockIdx.z;
    const int bh = b * H_ + h;
    const int row0 = c * W_ + qh * 128;
    const int wr = wid * 16;
    const int g = lane >> 2, tg = lane & 3;
    const int pqr0 = qh * 128 + wr + g;
    const int pqr1 = pqr0 + 8;
    const int wbase = qh * 128 + wr;

    const int eklo = W_ - c * W_;
    const int ekhi = S_ - 1 + W_ - c * W_;
    const int lo0 = max(pqr0, eklo), hi0 = min(pqr0 + 2 * W_, ekhi);
    const int lo1 = max(pqr1, eklo), hi1 = min(pqr1 + 2 * W_, ekhi);
    const int wlo = max(wbase, eklo);
    const int whi = min(wbase + 15 + 2 * W_, ekhi);

    int tlist[11], ntl = 0;
    tlist[ntl++] = 0;
    #pragma unroll
    for (int t = 1; t < 11; t++) {
        int ebase = qh * 128 + (t - 1) * 64;
        int kl = c * W_ + ebase - W_;
        if (kl + 63 >= 0 && kl < S_) tlist[ntl++] = t;
    }

    uint32_t qhi[4][4], qlo[4][4];
    {
        const __nv_bfloat16* Qh = &d_Qhi[((size_t)bh * S_ + row0 + wr) * 64];
        const __nv_bfloat16* Ql = &d_Qlo[((size_t)bh * S_ + row0 + wr) * 64];
        #pragma unroll
        for (int ks = 0; ks < 4; ks++) {
            int c0 = ks * 16 + tg * 2;
            qhi[ks][0] = *(const uint32_t*)&Qh[g * 64 + c0];
            qhi[ks][1] = *(const uint32_t*)&Qh[(g + 8) * 64 + c0];
            qhi[ks][2] = *(const uint32_t*)&Qh[g * 64 + c0 + 8];
            qhi[ks][3] = *(const uint32_t*)&Qh[(g + 8) * 64 + c0 + 8];
            qlo[ks][0] = *(const uint32_t*)&Ql[g * 64 + c0];
            qlo[ks][1] = *(const uint32_t*)&Ql[(g + 8) * 64 + c0];
            qlo[ks][2] = *(const uint32_t*)&Ql[g * 64 + c0 + 8];
            qlo[ks][3] = *(const uint32_t*)&Ql[(g + 8) * 64 + c0 + 8];
        }
    }

    float oacc[8][4];
    #pragma unroll
    for (int i = 0; i < 8; i++)
        #pragma unroll
        for (int r = 0; r < 4; r++) oacc[i][r] = 0.f;
    float lsum0 = 0.f, lsum1 = 0.f;

    const int lrowA = tid >> 3, lseg = tid & 7;
    const int lrowB = lrowA + 32;

    auto load_tile = [&](int stg, int t) {
        uint32_t base = sb + stg * BSTAGE;
        #pragma unroll
        for (int r = 0; r < 2; r++) {
            int row = r ? lrowB : lrowA;
            int ka = (t == 0) ? row
                              : (c * W_ + qh * 128 + (t - 1) * 64 + row - W_);
            int kr = min(max(ka, 0), S_ - 1);
            uint32_t off = row * 128 + ((lseg ^ (row & 7)) * 16);
            size_t src = ((size_t)bh * S_ + kr) * 64 + lseg * 8;
            CPA16(base + off, &d_Khi[src]);
            CPA16(base + BTILE + off, &d_Klo[src]);
            CPA16(base + 2 * BTILE + off, &d_Vhi[src]);
            CPA16(base + 3 * BTILE + off, &d_Vlo[src]);
        }
        CPA_COMMIT();
    };

    load_tile(0, tlist[0]);
    if (ntl > 1) load_tile(1, tlist[1]);

    int cur = 0;
    #pragma unroll 1
    for (int it = 0; it < ntl; it++) {
        const int t = tlist[it];
        if (it == ntl - 1) CPA_WAIT0(); else CPA_WAIT1();
        __syncthreads();
        if (it + 2 < ntl) {
            int nxt = cur + 2; if (nxt >= 3) nxt -= 3;
            load_tile(nxt, tlist[it + 2]);
        }

        const uint32_t sKhi = sb + cur * BSTAGE;
        const uint32_t sKlo = sKhi + BTILE;
        const uint32_t sVhi = sKhi + 2 * BTILE;
        const uint32_t sVlo = sKhi + 3 * BTILE;
        const int ebase = qh * 128 + (t - 1) * 64;

        const int nhalf = (t == 0) ? 1 : 2;
        for (int hf = 0; hf < nhalf; hf++) {
            const int kb = hf * 32;
            const int minE = ebase + kb, maxE = minE + 31;

            if (t != 0 && (maxE < wlo || minE > whi)) continue;

            float sc[4][4];
            #pragma unroll
            for (int i = 0; i < 4; i++)
                #pragma unroll
                for (int r = 0; r < 4; r++) sc[i][r] = 0.f;

            #pragma unroll
            for (int ks = 0; ks < 4; ks++) {
                uint32_t kh[2][4], kl[2][4];
                #pragma unroll
                for (int q2 = 0; q2 < 2; q2++) {
                    int row = kb + q2 * 16 + (lane & 7) + ((lane >> 4) << 3);
                    int seg = ks * 2 + ((lane >> 3) & 1);
                    uint32_t addr = row * 128 + ((seg ^ (row & 7)) * 16);
                    LDM4(kh[q2], sKhi + addr);
                    LDM4(kl[q2], sKlo + addr);
                }
                #pragma unroll
                for (int q2 = 0; q2 < 2; q2++)
                    #pragma unroll
                    for (int p = 0; p < 2; p++) {
                        int nt = q2 * 2 + p;
                        MMA16816(sc[nt], qhi[ks], kh[q2][p*2], kh[q2][p*2+1]);
                        MMA16816(sc[nt], qhi[ks], kl[q2][p*2], kl[q2][p*2+1]);
                        MMA16816(sc[nt], qlo[ks], kh[q2][p*2], kh[q2][p*2+1]);
                    }
            }

            const bool full = (t != 0) &&
                (minE >= wbase + 15) && (maxE <= wbase + 2 * W_) &&
                (minE >= eklo) && (maxE <= ekhi);

            uint32_t pah[2][4], pal[2][4];
            if (t == 0 || full) {
                #pragma unroll
                for (int nt = 0; nt < 4; nt++) {
                    float p00 = __expf(sc[nt][0]), p01 = __expf(sc[nt][1]);
                    float p10 = __expf(sc[nt][2]), p11 = __expf(sc[nt][3]);
                    lsum0 += p00 + p01;
                    lsum1 += p10 + p11;
                    __nv_bfloat16 h00 = __float2bfloat16(p00);
                    __nv_bfloat16 h01 = __float2bfloat16(p01);
                    __nv_bfloat16 h10 = __float2bfloat16(p10);
                    __nv_bfloat16 h11 = __float2bfloat16(p11);
                    __nv_bfloat162 hp0; hp0.x = h00; hp0.y = h01;
                    __nv_bfloat162 hp1; hp1.x = h10; hp1.y = h11;
                    __nv_bfloat162 lp0;
                    lp0.x = __float2bfloat16(p00 - __bfloat162float(h00));
                    lp0.y = __float2bfloat16(p01 - __bfloat162float(h01));
                    __nv_bfloat162 lp1;
                    lp1.x = __float2bfloat16(p10 - __bfloat162float(h10));
                    lp1.y = __float2bfloat16(p11 - __bfloat162float(h11));
                    pah[nt >> 1][(nt & 1) * 2 + 0] = *(uint32_t*)&hp0;
                    pah[nt >> 1][(nt & 1) * 2 + 1] = *(uint32_t*)&hp1;
                    pal[nt >> 1][(nt & 1) * 2 + 0] = *(uint32_t*)&lp0;
                    pal[nt >> 1][(nt & 1) * 2 + 1] = *(uint32_t*)&lp1;
                }
            } else {
                #pragma unroll
                for (int nt = 0; nt < 4; nt++) {
                    int e0 = ebase + kb + nt * 8 + tg * 2;
                    int e1 = e0 + 1;
                    float p00 = (e0 >= lo0 && e0 <= hi0) ? __expf(sc[nt][0]) : 0.f;
                    float p01 = (e1 >= lo0 && e1 <= hi0) ? __expf(sc[nt][1]) : 0.f;
                    float p10 = (e0 >= lo1 && e0 <= hi1) ? __expf(sc[nt][2]) : 0.f;
                    float p11 = (e1 >= lo1 && e1 <= hi1) ? __expf(sc[nt][3]) : 0.f;
                    lsum0 += p00 + p01;
                    lsum1 += p10 + p11;
                    __nv_bfloat16 h00 = __float2bfloat16(p00);
                    __nv_bfloat16 h01 = __float2bfloat16(p01);
                    __nv_bfloat16 h10 = __float2bfloat16(p10);
                    __nv_bfloat16 h11 = __float2bfloat16(p11);
                    __nv_bfloat162 hp0; hp0.x = h00; hp0.y = h01;
                    __nv_bfloat162 hp1; hp1.x = h10; hp1.y = h11;
                    __nv_bfloat162 lp0;
                    lp0.x = __float2bfloat16(p00 - __bfloat162float(h00));
                    lp0.y = __float2bfloat16(p01 - __bfloat162float(h01));
                    __nv_bfloat162 lp1;
                    lp1.x = __float2bfloat16(p10 - __bfloat162float(h10));
                    lp1.y = __float2bfloat16(p11 - __bfloat162float(h11));
                    pah[nt >> 1][(nt & 1) * 2 + 0] = *(uint32_t*)&hp0;
                    pah[nt >> 1][(nt & 1) * 2 + 1] = *(uint32_t*)&hp1;
                    pal[nt >> 1][(nt & 1) * 2 + 0] = *(uint32_t*)&lp0;
                    pal[nt >> 1][(nt & 1) * 2 + 1] = *(uint32_t*)&lp1;
                }
            }

            #pragma unroll
            for (int ksp = 0; ksp < 2; ksp++) {
                #pragma unroll
                for (int dg = 0; dg < 4; dg++) {
                    uint32_t vh[4], vl[4];
                    int row = kb + ksp * 16 + (lane & 15);
                    int seg = dg * 2 + (lane >> 4);
                    uint32_t addr = row * 128 + ((seg ^ (row & 7)) * 16);
                    LDM4T(vh, sVhi + addr);
                    LDM4T(vl, sVlo + addr);
                    MMA16816(oacc[dg * 2 + 0], pah[ksp], vh[0], vh[1]);
                    MMA16816(oacc[dg * 2 + 0], pal[ksp], vh[0], vh[1]);
                    MMA16816(oacc[dg * 2 + 0], pah[ksp], vl[0], vl[1]);
                    MMA16816(oacc[dg * 2 + 1], pah[ksp], vh[2], vh[3]);
                    MMA16816(oacc[dg * 2 + 1], pal[ksp], vh[2], vh[3]);
                    MMA16816(oacc[dg * 2 + 1], pah[ksp], vl[2], vl[3]);
                }
            }
        }
        cur++; if (cur >= 3) cur -= 3;
    }

    lsum0 += __shfl_xor_sync(0xffffffffu, lsum0, 1);
    lsum0 += __shfl_xor_sync(0xffffffffu, lsum0, 2);
    lsum1 += __shfl_xor_sync(0xffffffffu, lsum1, 1);
    lsum1 += __shfl_xor_sync(0xffffffffu, lsum1, 2);
    float inv0 = 1.f / lsum0, inv1 = 1.f / lsum1;
    float* o0 = &out[(size_t)(b * S_ + row0 + wr + g) * D_ + h * 64];
    float* o1 = o0 + 8 * D_;
    #pragma unroll
    for (int nt = 0; nt < 8; nt++) {
        float2 w0; w0.x = oacc[nt][0] * inv0; w0.y = oacc[nt][1] * inv0;
        float2 w1; w1.x = oacc[nt][2] * inv1; w1.y = oacc[nt][3] * inv1;
        *(float2*)&o0[nt * 8 + tg * 2] = w0;
        *(float2*)&o1[nt * 8 + tg * 2] = w1;
    }
}

// ---------------------------------------------------------------------------
extern "C" void kernel_launch(void* const* d_in, const int* in_sizes, int n_in,
                              void* d_out, int out_size)
{
    const float* hidden = (const float*)d_in[0];
    const float* Wq  = (const float*)d_in[1];
    const float* bq  = (const float*)d_in[2];
    const float* Wk  = (const float*)d_in[3];
    const float* bk  = (const float*)d_in[4];
    const float* Wv  = (const float*)d_in[5];
    const float* bv  = (const float*)d_in[6];
    const float* Wqg = (const float*)d_in[7];
    const float* bqg = (const float*)d_in[8];
    const float* Wkg = (const float*)d_in[9];
    const float* bkg = (const float*)d_in[10];
    const float* Wvg = (const float*)d_in[11];
    const float* bvg = (const float*)d_in[12];
    float* out = (float*)d_out;

    static cudaStream_t s2;
    static cudaEvent_t evA, evS2;
    static int configured = 0;
    if (!configured) {
        cudaFuncSetAttribute(gemm_kernel, cudaFuncAttributeMaxDynamicSharedMemorySize, GEMM_DYN);
        cudaFuncSetAttribute(band_mma_kernel, cudaFuncAttributeMaxDynamicSharedMemorySize, BAND_DYN);
        cudaStreamCreateWithFlags(&s2, cudaStreamNonBlocking);
        cudaEventCreateWithFlags(&evA, cudaEventDisableTiming);
        cudaEventCreateWithFlags(&evS2, cudaEventDisableTiming);
        configured = 1;
    }

    // stream0: prepasses, then the BAND-path projections (Q/K/V) ALONE
    convA_kernel<<<(B_*S_*D_)/1024, 256>>>(hidden);
    convW_kernel<<<dim3(24, 24, 6), dim3(32, 8)>>>(Wq, Wk, Wv, Wkg, Wvg, Wqg);
    gemm_kernel<<<dim3(6, 64, 3), 256, GEMM_DYN>>>(bq, bk, bv, bkg, bvg, bqg, 0);
    cudaEventRecord(evA, 0);

    // stream2 (forked AFTER gemmA): global-path projections + global attention,
    // overlapping band on stream0
    cudaStreamWaitEvent(s2, evA, 0);
    gemm_kernel<<<dim3(6, 64, 3), 256, GEMM_DYN, s2>>>(bq, bk, bv, bkg, bvg, bqg, 3);
    gattn_mma_kernel<<<dim3(8, H_, B_), 256, 0, s2>>>();
    cudaEventRecord(evS2, s2);

    // stream0: band attention (consumer of gemmA only)
    band_mma_kernel<<<dim3(NC_ * 2, H_, B_), 256, BAND_DYN>>>(out);

    // join, then combine (must follow band's writes to out rows < G)
    cudaStreamWaitEvent(0, evS2, 0);
    gattn_combine_kernel<<<B_ * H_ * G_, 64>>>(out);
}

// round 17
// speedup vs baseline: 1.4036x; 1.4036x over previous
#include <cuda_runtime.h>
#include <cuda_bf16.h>
#include <cuda_fp16.h>
#include <cstdint>

// Problem constants
#define B_  2
#define S_  4096
#define D_  768
#define H_  12
#define HD_ 64
#define W_  256
#define NC_ 16
#define G_  32
#define SCALE_ 0.125f

#define BHSD (B_*H_*S_*HD_)   // 6291456
#define NSPLITG 32

// ---------------------------------------------------------------------------
__device__ __forceinline__ uint32_t smem_u32(const void* p) {
    uint32_t a;
    asm("{ .reg .u64 t; cvta.to.shared.u64 t, %1; cvt.u32.u64 %0, t; }" : "=r"(a) : "l"(p));
    return a;
}
#define CPA16(sa, g) asm volatile("cp.async.cg.shared.global [%0], [%1], 16;" :: "r"(sa), "l"(g))
#define CPA_COMMIT() asm volatile("cp.async.commit_group;" ::: "memory")
#define CPA_WAIT1()  asm volatile("cp.async.wait_group 1;" ::: "memory")
#define CPA_WAIT0()  asm volatile("cp.async.wait_group 0;" ::: "memory")
#define LDM4(r, addr) \
  asm volatile("ldmatrix.sync.aligned.m8n8.x4.shared.b16 {%0,%1,%2,%3}, [%4];" \
    : "=r"((r)[0]), "=r"((r)[1]), "=r"((r)[2]), "=r"((r)[3]) : "r"(addr))
#define LDM4T(r, addr) \
  asm volatile("ldmatrix.sync.aligned.m8n8.x4.trans.shared.b16 {%0,%1,%2,%3}, [%4];" \
    : "=r"((r)[0]), "=r"((r)[1]), "=r"((r)[2]), "=r"((r)[3]) : "r"(addr))
#define MMA16816(d, a, b0, b1) \
  asm volatile("mma.sync.aligned.m16n8k16.row.col.f32.bf16.bf16.f32 " \
    "{%0,%1,%2,%3}, {%4,%5,%6,%7}, {%8,%9}, {%0,%1,%2,%3};" \
    : "+f"((d)[0]), "+f"((d)[1]), "+f"((d)[2]), "+f"((d)[3]) \
    : "r"((a)[0]), "r"((a)[1]), "r"((a)[2]), "r"((a)[3]), "r"(b0), "r"(b1))
#define MMA16816H(d, a, b0, b1) \
  asm volatile("mma.sync.aligned.m16n8k16.row.col.f32.f16.f16.f32 " \
    "{%0,%1,%2,%3}, {%4,%5,%6,%7}, {%8,%9}, {%0,%1,%2,%3};" \
    : "+f"((d)[0]), "+f"((d)[1]), "+f"((d)[2]), "+f"((d)[3]) \
    : "r"((a)[0]), "r"((a)[1]), "r"((a)[2]), "r"((a)[3]), "r"(b0), "r"(b1))

// 64B-row swizzle (conflict-free for ldmatrix + cp.async)
#define SWZ64(row, seg) ((uint32_t)((row) * 64 + ((((seg) ^ ((row) >> 1)) & 3) * 16)))

// ---------------------------------------------------------------------------
// Device scratch
__device__ __half d_Qf[BHSD], d_Kf[BHSD], d_Kgf[BHSD];      // single fp16
__device__ __half d_qgf[B_*H_*G_*HD_];
__device__ __nv_bfloat16 d_Vhi[BHSD], d_Vlo[BHSD];          // hi/lo bf16
__device__ __nv_bfloat16 d_Vghi[BHSD], d_Vglo[BHSD];
__device__ __nv_bfloat16 d_Ahi[B_*S_*D_], d_Alo[B_*S_*D_];
__device__ __half        d_Af16[B_*S_*D_];
__device__ __nv_bfloat16 d_Whi[6][D_*D_], d_Wlo[6][D_*D_];  // transposed [n][k]
__device__ __half        d_Wf16[6][D_*D_];
__device__ float d_lpart[B_*H_*NSPLITG*G_];
__device__ float d_accpart[B_*H_*NSPLITG*G_*HD_];

// ---------------------------------------------------------------------------
// Prepass: hidden -> bf16 hi/lo + fp16 single
__global__ __launch_bounds__(256) void convA_kernel(const float* __restrict__ A)
{
    int i = (blockIdx.x * 256 + threadIdx.x) * 4;
    float4 a = *(const float4*)&A[i];
    float av[4] = {a.x, a.y, a.z, a.w};
    __nv_bfloat16 h[4], l[4];
    __half f[4];
    #pragma unroll
    for (int j = 0; j < 4; j++) {
        h[j] = __float2bfloat16(av[j]);
        l[j] = __float2bfloat16(av[j] - __bfloat162float(h[j]));
        f[j] = __float2half_rn(av[j]);
    }
    *(uint2*)&d_Ahi[i] = *(uint2*)h;
    *(uint2*)&d_Alo[i] = *(uint2*)l;
    *(uint2*)&d_Af16[i] = *(uint2*)f;
}

// Prepass: W[k][n] -> transposed bf16 hi/lo + fp16 single
__global__ __launch_bounds__(256) void convW_kernel(
    const float* __restrict__ W0, const float* __restrict__ W1,
    const float* __restrict__ W2, const float* __restrict__ W3,
    const float* __restrict__ W4, const float* __restrict__ W5)
{
    __shared__ float t[32][33];
    const int which = blockIdx.z;
    const float* __restrict__ W = (which == 0) ? W0 : (which == 1) ? W1
                                : (which == 2) ? W2 : (which == 3) ? W3
                                : (which == 4) ? W4 : W5;
    const int n0 = blockIdx.x * 32, k0 = blockIdx.y * 32;
    const int tx = threadIdx.x, ty = threadIdx.y;
    #pragma unroll
    for (int r = 0; r < 32; r += 8)
        t[ty + r][tx] = W[(k0 + ty + r) * D_ + n0 + tx];
    __syncthreads();
    #pragma unroll
    for (int r = 0; r < 32; r += 8) {
        float v = t[tx][ty + r];
        __nv_bfloat16 hh = __float2bfloat16(v);
        d_Whi[which][(n0 + ty + r) * D_ + k0 + tx] = hh;
        d_Wlo[which][(n0 + ty + r) * D_ + k0 + tx] =
            __float2bfloat16(v - __bfloat162float(hh));
        d_Wf16[which][(n0 + ty + r) * D_ + k0 + tx] = __float2half_rn(v);
    }
}

// ---------------------------------------------------------------------------
// 3-term bf16 hi/lo GEMM for V (which=2) and Vg (which=4).
// ---------------------------------------------------------------------------
#define GTILE 8192
#define GSTAGE (4 * GTILE)
#define GEMM_DYN (3 * GSTAGE)      // 98304

__global__ __launch_bounds__(256, 2) void gemm3_kernel(
    const float* __restrict__ bias, int which)
{
    extern __shared__ char smraw[];
    const uint32_t sb = smem_u32(smraw);
    const int tid = threadIdx.x, wid = tid >> 5, lane = tid & 31;
    const int mw = wid & 3, nw = wid >> 2;
    const int n0 = blockIdx.x * 128;
    const int m0 = blockIdx.y * 128;
    const __nv_bfloat16* __restrict__ Ahi = d_Ahi;
    const __nv_bfloat16* __restrict__ Alo = d_Alo;
    const __nv_bfloat16* __restrict__ Whi = d_Whi[which];
    const __nv_bfloat16* __restrict__ Wlo = d_Wlo[which];

    float acc[2][8][4];
    #pragma unroll
    for (int mt = 0; mt < 2; mt++)
        #pragma unroll
        for (int nt = 0; nt < 8; nt++)
            #pragma unroll
            for (int r = 0; r < 4; r++) acc[mt][nt][r] = 0.f;

    const int lrow = tid >> 2, lch = tid & 3;
    const int lrow2 = lrow + 64;
    const uint32_t o1 = SWZ64(lrow, lch), o2 = SWZ64(lrow2, lch);

    auto load_chunk = [&](int buf, int k0) {
        uint32_t base = sb + buf * GSTAGE;
        CPA16(base + o1, &Ahi[(m0 + lrow) * D_ + k0 + lch * 8]);
        CPA16(base + o2, &Ahi[(m0 + lrow2) * D_ + k0 + lch * 8]);
        base += GTILE;
        CPA16(base + o1, &Alo[(m0 + lrow) * D_ + k0 + lch * 8]);
        CPA16(base + o2, &Alo[(m0 + lrow2) * D_ + k0 + lch * 8]);
        base += GTILE;
        CPA16(base + o1, &Whi[(n0 + lrow) * D_ + k0 + lch * 8]);
        CPA16(base + o2, &Whi[(n0 + lrow2) * D_ + k0 + lch * 8]);
        base += GTILE;
        CPA16(base + o1, &Wlo[(n0 + lrow) * D_ + k0 + lch * 8]);
        CPA16(base + o2, &Wlo[(n0 + lrow2) * D_ + k0 + lch * 8]);
        CPA_COMMIT();
    };

    load_chunk(0, 0);
    load_chunk(1, 32);

    int cur = 0;
    #pragma unroll 1
    for (int c = 0; c < 24; c++) {
        if (c == 23) CPA_WAIT0(); else CPA_WAIT1();
        __syncthreads();
        if (c + 2 < 24) {
            int nxt = cur + 2; if (nxt >= 3) nxt -= 3;
            load_chunk(nxt, (c + 2) * 32);
        }

        const uint32_t aBase  = sb + cur * GSTAGE;
        const uint32_t alBase = aBase + GTILE;
        const uint32_t bBase  = aBase + 2 * GTILE;
        const uint32_t blBase = aBase + 3 * GTILE;

        #pragma unroll
        for (int ks = 0; ks < 2; ks++) {
            uint32_t ahi[2][4], alo[2][4];
            const int aseg = ks * 2 + ((lane >> 4) & 1);
            #pragma unroll
            for (int mt = 0; mt < 2; mt++) {
                int row = mw * 32 + mt * 16 + (lane & 15);
                LDM4(ahi[mt], aBase + SWZ64(row, aseg));
                LDM4(alo[mt], alBase + SWZ64(row, aseg));
            }
            const int bseg = ks * 2 + ((lane >> 3) & 1);
            #pragma unroll
            for (int nh = 0; nh < 2; nh++) {
                uint32_t bhi[2][4], blo[2][4];
                #pragma unroll
                for (int q = 0; q < 2; q++) {
                    int row = nw * 64 + nh * 32 + q * 16 + (lane & 7) + ((lane >> 4) << 3);
                    LDM4(bhi[q], bBase + SWZ64(row, bseg));
                    LDM4(blo[q], blBase + SWZ64(row, bseg));
                }
                #pragma unroll
                for (int mt = 0; mt < 2; mt++)
                    #pragma unroll
                    for (int q = 0; q < 2; q++)
                        #pragma unroll
                        for (int p = 0; p < 2; p++) {
                            int nt = nh * 4 + q * 2 + p;
                            MMA16816(acc[mt][nt], ahi[mt], bhi[q][p*2], bhi[q][p*2+1]);
                            MMA16816(acc[mt][nt], ahi[mt], blo[q][p*2], blo[q][p*2+1]);
                            MMA16816(acc[mt][nt], alo[mt], bhi[q][p*2], bhi[q][p*2+1]);
                        }
            }
        }
        cur++; if (cur >= 3) cur -= 3;
    }

    const int g = lane >> 2, tg = lane & 3;
    #pragma unroll
    for (int mt = 0; mt < 2; mt++)
        #pragma unroll
        for (int half = 0; half < 2; half++) {
            int m = m0 + mw * 32 + mt * 16 + g + half * 8;
            int b = m >> 12, s = m & 4095;
            #pragma unroll
            for (int nt = 0; nt < 8; nt++) {
                int n = n0 + nw * 64 + nt * 8 + tg * 2;
                float v0 = acc[mt][nt][half * 2 + 0] + bias[n];
                float v1 = acc[mt][nt][half * 2 + 1] + bias[n + 1];
                int h = n >> 6, hd = n & 63;
                __nv_bfloat16 h0 = __float2bfloat16(v0);
                __nv_bfloat16 h1 = __float2bfloat16(v1);
                __nv_bfloat162 hp; hp.x = h0; hp.y = h1;
                __nv_bfloat162 lp;
                lp.x = __float2bfloat16(v0 - __bfloat162float(h0));
                lp.y = __float2bfloat16(v1 - __bfloat162float(h1));
                size_t bidx = ((size_t)(b * H_ + h) * S_ + s) * HD_ + hd;
                if (which == 2) {
                    *(__nv_bfloat162*)&d_Vhi[bidx] = hp;
                    *(__nv_bfloat162*)&d_Vlo[bidx] = lp;
                } else {
                    *(__nv_bfloat162*)&d_Vghi[bidx] = hp;
                    *(__nv_bfloat162*)&d_Vglo[bidx] = lp;
                }
            }
        }
}

// ---------------------------------------------------------------------------
// 1-term fp16 GEMM for Q (0), K (1), Kg (3), qg (5).
// grid = (6, 64, 2): which = z ? w1 : w0.
// ---------------------------------------------------------------------------
#define G1STAGE (2 * GTILE)
#define GEMM1_DYN (3 * G1STAGE)    // 49152

__global__ __launch_bounds__(256, 2) void gemm1_kernel(
    const float* __restrict__ bq, const float* __restrict__ bk,
    const float* __restrict__ bkg, const float* __restrict__ bqg,
    int w0, int w1)
{
    const int which = blockIdx.z ? w1 : w0;
    if (which == 5 && blockIdx.y != 0 && blockIdx.y != 32) return;
    extern __shared__ char smraw[];
    const uint32_t sb = smem_u32(smraw);
    const int tid = threadIdx.x, wid = tid >> 5, lane = tid & 31;
    const int mw = wid & 3, nw = wid >> 2;
    const int n0 = blockIdx.x * 128;
    const int m0 = blockIdx.y * 128;
    const float* bias = (which == 0) ? bq : (which == 1) ? bk
                       : (which == 3) ? bkg : bqg;
    const __half* __restrict__ Af = d_Af16;
    const __half* __restrict__ Wf = d_Wf16[which];

    float acc[2][8][4];
    #pragma unroll
    for (int mt = 0; mt < 2; mt++)
        #pragma unroll
        for (int nt = 0; nt < 8; nt++)
            #pragma unroll
            for (int r = 0; r < 4; r++) acc[mt][nt][r] = 0.f;

    const int lrow = tid >> 2, lch = tid & 3;
    const int lrow2 = lrow + 64;
    const uint32_t o1 = SWZ64(lrow, lch), o2 = SWZ64(lrow2, lch);

    auto load_chunk = [&](int buf, int k0) {
        uint32_t base = sb + buf * G1STAGE;
        CPA16(base + o1, &Af[(m0 + lrow) * D_ + k0 + lch * 8]);
        CPA16(base + o2, &Af[(m0 + lrow2) * D_ + k0 + lch * 8]);
        base += GTILE;
        CPA16(base + o1, &Wf[(n0 + lrow) * D_ + k0 + lch * 8]);
        CPA16(base + o2, &Wf[(n0 + lrow2) * D_ + k0 + lch * 8]);
        CPA_COMMIT();
    };

    load_chunk(0, 0);
    load_chunk(1, 32);

    int cur = 0;
    #pragma unroll 1
    for (int c = 0; c < 24; c++) {
        if (c == 23) CPA_WAIT0(); else CPA_WAIT1();
        __syncthreads();
        if (c + 2 < 24) {
            int nxt = cur + 2; if (nxt >= 3) nxt -= 3;
            load_chunk(nxt, (c + 2) * 32);
        }

        const uint32_t aBase = sb + cur * G1STAGE;
        const uint32_t bBase = aBase + GTILE;

        #pragma unroll
        for (int ks = 0; ks < 2; ks++) {
            uint32_t af[2][4];
            const int aseg = ks * 2 + ((lane >> 4) & 1);
            #pragma unroll
            for (int mt = 0; mt < 2; mt++) {
                int row = mw * 32 + mt * 16 + (lane & 15);
                LDM4(af[mt], aBase + SWZ64(row, aseg));
            }
            const int bseg = ks * 2 + ((lane >> 3) & 1);
            #pragma unroll
            for (int nh = 0; nh < 2; nh++) {
                uint32_t bf[2][4];
                #pragma unroll
                for (int q = 0; q < 2; q++) {
                    int row = nw * 64 + nh * 32 + q * 16 + (lane & 7) + ((lane >> 4) << 3);
                    LDM4(bf[q], bBase + SWZ64(row, bseg));
                }
                #pragma unroll
                for (int mt = 0; mt < 2; mt++)
                    #pragma unroll
                    for (int q = 0; q < 2; q++)
                        #pragma unroll
                        for (int p = 0; p < 2; p++)
                            MMA16816H(acc[mt][nh * 4 + q * 2 + p], af[mt],
                                      bf[q][p*2], bf[q][p*2+1]);
            }
        }
        cur++; if (cur >= 3) cur -= 3;
    }

    const int g = lane >> 2, tg = lane & 3;
    #pragma unroll
    for (int mt = 0; mt < 2; mt++)
        #pragma unroll
        for (int half = 0; half < 2; half++) {
            int m = m0 + mw * 32 + mt * 16 + g + half * 8;
            int b = m >> 12, s = m & 4095;
            #pragma unroll
            for (int nt = 0; nt < 8; nt++) {
                int n = n0 + nw * 64 + nt * 8 + tg * 2;
                float v0 = acc[mt][nt][half * 2 + 0] + bias[n];
                float v1 = acc[mt][nt][half * 2 + 1] + bias[n + 1];
                int h = n >> 6, hd = n & 63;
                if (which == 0 || which == 5) { v0 *= SCALE_; v1 *= SCALE_; }
                if (which == 5 && s >= G_) continue;
                __half2 fp; fp.x = __float2half_rn(v0); fp.y = __float2half_rn(v1);
                size_t bidx = ((size_t)(b * H_ + h) * S_ + s) * HD_ + hd;
                if (which == 0)      *(__half2*)&d_Qf[bidx] = fp;
                else if (which == 1) *(__half2*)&d_Kf[bidx] = fp;
                else if (which == 3) *(__half2*)&d_Kgf[bidx] = fp;
                else {
                    size_t qidx = ((size_t)(b * H_ + h) * G_ + s) * HD_ + hd;
                    *(__half2*)&d_qgf[qidx] = fp;
                }
            }
        }
}

// ---------------------------------------------------------------------------
// Global attention: QK single fp16 (1 MMA), PV bf16 hi/lo (3 MMAs).
// ---------------------------------------------------------------------------
__global__ __launch_bounds__(256, 2) void gattn_mma_kernel()
{
    __shared__ __align__(16) char kf_sm[16384];
    __shared__ __align__(16) char vh_sm[16384];
    __shared__ __align__(16) char vl_sm[16384];
    const uint32_t sKf = smem_u32(kf_sm);
    const uint32_t sVhi = smem_u32(vh_sm), sVlo = smem_u32(vl_sm);
    const int tid = threadIdx.x, wid = tid >> 5, lane = tid & 31;
    const int sp = blockIdx.x, h = blockIdx.y, b = blockIdx.z;
    const int bh = b * H_ + h;
    const int mw = wid & 1, kw = wid >> 1;
    const int g = lane >> 2, tg = lane & 3;

    uint32_t qf[4][4];
    {
        const __half* Qh = &d_qgf[((size_t)bh * G_ + mw * 16) * 64];
        #pragma unroll
        for (int ks = 0; ks < 4; ks++) {
            int c0 = ks * 16 + tg * 2;
            qf[ks][0] = *(const uint32_t*)&Qh[g * 64 + c0];
            qf[ks][1] = *(const uint32_t*)&Qh[(g + 8) * 64 + c0];
            qf[ks][2] = *(const uint32_t*)&Qh[g * 64 + c0 + 8];
            qf[ks][3] = *(const uint32_t*)&Qh[(g + 8) * 64 + c0 + 8];
        }
    }

    float oacc[8][4];
    #pragma unroll
    for (int i = 0; i < 8; i++)
        #pragma unroll
        for (int r = 0; r < 4; r++) oacc[i][r] = 0.f;
    float lsum0 = 0.f, lsum1 = 0.f;

    #pragma unroll 1
    for (int ch = 0; ch < 4; ch++) {
        __syncthreads();
        #pragma unroll
        for (int r = 0; r < 4; r++) {
            int idx = tid + r * 256;
            int row = idx >> 3, seg = idx & 7;
            uint32_t off = row * 128 + ((seg ^ (row & 7)) * 16);
            size_t src = ((size_t)bh * S_ + sp * 512 + ch * 128 + row) * 64 + seg * 8;
            CPA16(sKf + off, &d_Kgf[src]);
            CPA16(sVhi + off, &d_Vghi[src]);
            CPA16(sVlo + off, &d_Vglo[src]);
        }
        CPA_COMMIT(); CPA_WAIT0();
        __syncthreads();

        const int kb = kw * 32;
        float sc[4][4];
        #pragma unroll
        for (int i = 0; i < 4; i++)
            #pragma unroll
            for (int r = 0; r < 4; r++) sc[i][r] = 0.f;

        #pragma unroll
        for (int ks = 0; ks < 4; ks++) {
            uint32_t kf[2][4];
            #pragma unroll
            for (int q2 = 0; q2 < 2; q2++) {
                int row = kb + q2 * 16 + (lane & 7) + ((lane >> 4) << 3);
                int seg = ks * 2 + ((lane >> 3) & 1);
                uint32_t addr = row * 128 + ((seg ^ (row & 7)) * 16);
                LDM4(kf[q2], sKf + addr);
            }
            #pragma unroll
            for (int q2 = 0; q2 < 2; q2++)
                #pragma unroll
                for (int p = 0; p < 2; p++)
                    MMA16816H(sc[q2 * 2 + p], qf[ks], kf[q2][p*2], kf[q2][p*2+1]);
        }

        uint32_t pah[2][4], pal[2][4];
        #pragma unroll
        for (int nt = 0; nt < 4; nt++) {
            float p00 = __expf(sc[nt][0]), p01 = __expf(sc[nt][1]);
            float p10 = __expf(sc[nt][2]), p11 = __expf(sc[nt][3]);
            lsum0 += p00 + p01;
            lsum1 += p10 + p11;
            __nv_bfloat16 h00 = __float2bfloat16(p00);
            __nv_bfloat16 h01 = __float2bfloat16(p01);
            __nv_bfloat16 h10 = __float2bfloat16(p10);
            __nv_bfloat16 h11 = __float2bfloat16(p11);
            __nv_bfloat162 hp0; hp0.x = h00; hp0.y = h01;
            __nv_bfloat162 hp1; hp1.x = h10; hp1.y = h11;
            __nv_bfloat162 lp0;
            lp0.x = __float2bfloat16(p00 - __bfloat162float(h00));
            lp0.y = __float2bfloat16(p01 - __bfloat162float(h01));
            __nv_bfloat162 lp1;
            lp1.x = __float2bfloat16(p10 - __bfloat162float(h10));
            lp1.y = __float2bfloat16(p11 - __bfloat162float(h11));
            pah[nt >> 1][(nt & 1) * 2 + 0] = *(uint32_t*)&hp0;
            pah[nt >> 1][(nt & 1) * 2 + 1] = *(uint32_t*)&hp1;
            pal[nt >> 1][(nt & 1) * 2 + 0] = *(uint32_t*)&lp0;
            pal[nt >> 1][(nt & 1) * 2 + 1] = *(uint32_t*)&lp1;
        }

        #pragma unroll
        for (int ksp = 0; ksp < 2; ksp++) {
            #pragma unroll
            for (int dg = 0; dg < 4; dg++) {
                uint32_t vh[4], vl[4];
                int row = kb + ksp * 16 + (lane & 15);
                int seg = dg * 2 + (lane >> 4);
                uint32_t addr = row * 128 + ((seg ^ (row & 7)) * 16);
                LDM4T(vh, sVhi + addr);
                LDM4T(vl, sVlo + addr);
                MMA16816(oacc[dg * 2 + 0], pah[ksp], vh[0], vh[1]);
                MMA16816(oacc[dg * 2 + 0], pal[ksp], vh[0], vh[1]);
                MMA16816(oacc[dg * 2 + 0], pah[ksp], vl[0], vl[1]);
                MMA16816(oacc[dg * 2 + 1], pah[ksp], vh[2], vh[3]);
                MMA16816(oacc[dg * 2 + 1], pal[ksp], vh[2], vh[3]);
                MMA16816(oacc[dg * 2 + 1], pah[ksp], vl[2], vl[3]);
            }
        }
    }

    lsum0 += __shfl_xor_sync(0xffffffffu, lsum0, 1);
    lsum0 += __shfl_xor_sync(0xffffffffu, lsum0, 2);
    lsum1 += __shfl_xor_sync(0xffffffffu, lsum1, 1);
    lsum1 += __shfl_xor_sync(0xffffffffu, lsum1, 2);
    const int part = sp * 4 + kw;
    const int r0 = mw * 16 + g, r1 = r0 + 8;
    if (tg == 0) {
        d_lpart[((size_t)bh * NSPLITG + part) * G_ + r0] = lsum0;
        d_lpart[((size_t)bh * NSPLITG + part) * G_ + r1] = lsum1;
    }
    float* a0 = &d_accpart[(((size_t)bh * NSPLITG + part) * G_ + r0) * HD_];
    float* a1 = &d_accpart[(((size_t)bh * NSPLITG + part) * G_ + r1) * HD_];
    #pragma unroll
    for (int nt = 0; nt < 8; nt++) {
        float2 w0; w0.x = oacc[nt][0]; w0.y = oacc[nt][1];
        float2 w1; w1.x = oacc[nt][2]; w1.y = oacc[nt][3];
        *(float2*)&a0[nt * 8 + tg * 2] = w0;
        *(float2*)&a1[nt * 8 + tg * 2] = w1;
    }
}

__global__ __launch_bounds__(64) void gattn_combine_kernel(float* __restrict__ out)
{
    const int idx = blockIdx.x;
    const int bh = idx >> 5;
    const int g = idx & 31;
    const int b = bh / H_, h = bh % H_;
    const int d = threadIdx.x;
    float l = 0.f, a = 0.f;
    #pragma unroll
    for (int sp = 0; sp < NSPLITG; sp++) {
        l += d_lpart[((size_t)bh * NSPLITG + sp) * G_ + g];
        a += d_accpart[(((size_t)bh * NSPLITG + sp) * G_ + g) * HD_ + d];
    }
    out[(b * S_ + g) * D_ + h * HD_ + d] = a / l;
}

// ---------------------------------------------------------------------------
// Band attention: QK single fp16, PV bf16 hi/lo. 3-stage pipeline, skip/fast/
// masked paths as before.
// ---------------------------------------------------------------------------
#define BTILE 8192
#define BSTAGE (3 * BTILE)
#define BAND_DYN (3 * BSTAGE)     // 73728

__global__ __launch_bounds__(256, 2) void band_mma_kernel(float* __restrict__ out)
{
    extern __shared__ char bsm[];
    const uint32_t sb = smem_u32(bsm);
    const int tid = threadIdx.x, wid = tid >> 5, lane = tid & 31;
    const int c = blockIdx.x >> 1, qh = blockIdx.x & 1;
    const int h = blockIdx.y, b = blockIdx.z;
    const int bh = b * H_ + h;
    const int row0 = c * W_ + qh * 128;
    const int wr = wid * 16;
    const int g = lane >> 2, tg = lane & 3;
    const int pqr0 = qh * 128 + wr + g;
    const int pqr1 = pqr0 + 8;
    const int wbase = qh * 128 + wr;

    const int eklo = W_ - c * W_;
    const int ekhi = S_ - 1 + W_ - c * W_;
    const int lo0 = max(pqr0, eklo), hi0 = min(pqr0 + 2 * W_, ekhi);
    const int lo1 = max(pqr1, eklo), hi1 = min(pqr1 + 2 * W_, ekhi);
    const int wlo = max(wbase, eklo);
    const int whi = min(wbase + 15 + 2 * W_, ekhi);

    int tlist[11], ntl = 0;
    tlist[ntl++] = 0;
    #pragma unroll
    for (int t = 1; t < 11; t++) {
        int ebase = qh * 128 + (t - 1) * 64;
        int kl = c * W_ + ebase - W_;
        if (kl + 63 >= 0 && kl < S_) tlist[ntl++] = t;
    }

    uint32_t qf[4][4];
    {
        const __half* Qh = &d_Qf[((size_t)bh * S_ + row0 + wr) * 64];
        #pragma unroll
        for (int ks = 0; ks < 4; ks++) {
            int c0 = ks * 16 + tg * 2;
            qf[ks][0] = *(const uint32_t*)&Qh[g * 64 + c0];
            qf[ks][1] = *(const uint32_t*)&Qh[(g + 8) * 64 + c0];
            qf[ks][2] = *(const uint32_t*)&Qh[g * 64 + c0 + 8];
            qf[ks][3] = *(const uint32_t*)&Qh[(g + 8) * 64 + c0 + 8];
        }
    }

    float oacc[8][4];
    #pragma unroll
    for (int i = 0; i < 8; i++)
        #pragma unroll
        for (int r = 0; r < 4; r++) oacc[i][r] = 0.f;
    float lsum0 = 0.f, lsum1 = 0.f;

    const int lrowA = tid >> 3, lseg = tid & 7;
    const int lrowB = lrowA + 32;

    auto load_tile = [&](int stg, int t) {
        uint32_t base = sb + stg * BSTAGE;
        #pragma unroll
        for (int r = 0; r < 2; r++) {
            int row = r ? lrowB : lrowA;
            int ka = (t == 0) ? row
                              : (c * W_ + qh * 128 + (t - 1) * 64 + row - W_);
            int kr = min(max(ka, 0), S_ - 1);
            uint32_t off = row * 128 + ((lseg ^ (row & 7)) * 16);
            size_t src = ((size_t)bh * S_ + kr) * 64 + lseg * 8;
            CPA16(base + off, &d_Kf[src]);
            CPA16(base + BTILE + off, &d_Vhi[src]);
            CPA16(base + 2 * BTILE + off, &d_Vlo[src]);
        }
        CPA_COMMIT();
    };

    load_tile(0, tlist[0]);
    if (ntl > 1) load_tile(1, tlist[1]);

    int cur = 0;
    #pragma unroll 1
    for (int it = 0; it < ntl; it++) {
        const int t = tlist[it];
        if (it == ntl - 1) CPA_WAIT0(); else CPA_WAIT1();
        __syncthreads();
        if (it + 2 < ntl) {
            int nxt = cur + 2; if (nxt >= 3) nxt -= 3;
            load_tile(nxt, tlist[it + 2]);
        }

        const uint32_t sKf  = sb + cur * BSTAGE;
        const uint32_t sVhi = sKf + BTILE;
        const uint32_t sVlo = sKf + 2 * BTILE;
        const int ebase = qh * 128 + (t - 1) * 64;

        const int nhalf = (t == 0) ? 1 : 2;
        for (int hf = 0; hf < nhalf; hf++) {
            const int kb = hf * 32;
            const int minE = ebase + kb, maxE = minE + 31;

            if (t != 0 && (maxE < wlo || minE > whi)) continue;

            float sc[4][4];
            #pragma unroll
            for (int i = 0; i < 4; i++)
                #pragma unroll
                for (int r = 0; r < 4; r++) sc[i][r] = 0.f;

            #pragma unroll
            for (int ks = 0; ks < 4; ks++) {
                uint32_t kf[2][4];
                #pragma unroll
                for (int q2 = 0; q2 < 2; q2++) {
                    int row = kb + q2 * 16 + (lane & 7) + ((lane >> 4) << 3);
                    int seg = ks * 2 + ((lane >> 3) & 1);
                    uint32_t addr = row * 128 + ((seg ^ (row & 7)) * 16);
                    LDM4(kf[q2], sKf + addr);
                }
                #pragma unroll
                for (int q2 = 0; q2 < 2; q2++)
                    #pragma unroll
                    for (int p = 0; p < 2; p++)
                        MMA16816H(sc[q2 * 2 + p], qf[ks], kf[q2][p*2], kf[q2][p*2+1]);
            }

            const bool full = (t != 0) &&
                (minE >= wbase + 15) && (maxE <= wbase + 2 * W_) &&
                (minE >= eklo) && (maxE <= ekhi);

            uint32_t pah[2][4], pal[2][4];
            if (t == 0 || full) {
                #pragma unroll
                for (int nt = 0; nt < 4; nt++) {
                    float p00 = __expf(sc[nt][0]), p01 = __expf(sc[nt][1]);
                    float p10 = __expf(sc[nt][2]), p11 = __expf(sc[nt][3]);
                    lsum0 += p00 + p01;
                    lsum1 += p10 + p11;
                    __nv_bfloat16 h00 = __float2bfloat16(p00);
                    __nv_bfloat16 h01 = __float2bfloat16(p01);
                    __nv_bfloat16 h10 = __float2bfloat16(p10);
                    __nv_bfloat16 h11 = __float2bfloat16(p11);
                    __nv_bfloat162 hp0; hp0.x = h00; hp0.y = h01;
                    __nv_bfloat162 hp1; hp1.x = h10; hp1.y = h11;
                    __nv_bfloat162 lp0;
                    lp0.x = __float2bfloat16(p00 - __bfloat162float(h00));
                    lp0.y = __float2bfloat16(p01 - __bfloat162float(h01));
                    __nv_bfloat162 lp1;
                    lp1.x = __float2bfloat16(p10 - __bfloat162float(h10));
                    lp1.y = __float2bfloat16(p11 - __bfloat162float(h11));
                    pah[nt >> 1][(nt & 1) * 2 + 0] = *(uint32_t*)&hp0;
                    pah[nt >> 1][(nt & 1) * 2 + 1] = *(uint32_t*)&hp1;
                    pal[nt >> 1][(nt & 1) * 2 + 0] = *(uint32_t*)&lp0;
                    pal[nt >> 1][(nt & 1) * 2 + 1] = *(uint32_t*)&lp1;
                }
            } else {
                #pragma unroll
                for (int nt = 0; nt < 4; nt++) {
                    int e0 = ebase + kb + nt * 8 + tg * 2;
                    int e1 = e0 + 1;
                    float p00 = (e0 >= lo0 && e0 <= hi0) ? __expf(sc[nt][0]) : 0.f;
                    float p01 = (e1 >= lo0 && e1 <= hi0) ? __expf(sc[nt][1]) : 0.f;
                    float p10 = (e0 >= lo1 && e0 <= hi1) ? __expf(sc[nt][2]) : 0.f;
                    float p11 = (e1 >= lo1 && e1 <= hi1) ? __expf(sc[nt][3]) : 0.f;
                    lsum0 += p00 + p01;
                    lsum1 += p10 + p11;
                    __nv_bfloat16 h00 = __float2bfloat16(p00);
                    __nv_bfloat16 h01 = __float2bfloat16(p01);
                    __nv_bfloat16 h10 = __float2bfloat16(p10);
                    __nv_bfloat16 h11 = __float2bfloat16(p11);
                    __nv_bfloat162 hp0; hp0.x = h00; hp0.y = h01;
                    __nv_bfloat162 hp1; hp1.x = h10; hp1.y = h11;
                    __nv_bfloat162 lp0;
                    lp0.x = __float2bfloat16(p00 - __bfloat162float(h00));
                    lp0.y = __float2bfloat16(p01 - __bfloat162float(h01));
                    __nv_bfloat162 lp1;
                    lp1.x = __float2bfloat16(p10 - __bfloat162float(h10));
                    lp1.y = __float2bfloat16(p11 - __bfloat162float(h11));
                    pah[nt >> 1][(nt & 1) * 2 + 0] = *(uint32_t*)&hp0;
                    pah[nt >> 1][(nt & 1) * 2 + 1] = *(uint32_t*)&hp1;
                    pal[nt >> 1][(nt & 1) * 2 + 0] = *(uint32_t*)&lp0;
                    pal[nt >> 1][(nt & 1) * 2 + 1] = *(uint32_t*)&lp1;
                }
            }

            #pragma unroll
            for (int ksp = 0; ksp < 2; ksp++) {
                #pragma unroll
                for (int dg = 0; dg < 4; dg++) {
                    uint32_t vh[4], vl[4];
                    int row = kb + ksp * 16 + (lane & 15);
                    int seg = dg * 2 + (lane >> 4);
                    uint32_t addr = row * 128 + ((seg ^ (row & 7)) * 16);
                    LDM4T(vh, sVhi + addr);
                    LDM4T(vl, sVlo + addr);
                    MMA16816(oacc[dg * 2 + 0], pah[ksp], vh[0], vh[1]);
                    MMA16816(oacc[dg * 2 + 0], pal[ksp], vh[0], vh[1]);
                    MMA16816(oacc[dg * 2 + 0], pah[ksp], vl[0], vl[1]);
                    MMA16816(oacc[dg * 2 + 1], pah[ksp], vh[2], vh[3]);
                    MMA16816(oacc[dg * 2 + 1], pal[ksp], vh[2], vh[3]);
                    MMA16816(oacc[dg * 2 + 1], pah[ksp], vl[2], vl[3]);
                }
            }
        }
        cur++; if (cur >= 3) cur -= 3;
    }

    lsum0 += __shfl_xor_sync(0xffffffffu, lsum0, 1);
    lsum0 += __shfl_xor_sync(0xffffffffu, lsum0, 2);
    lsum1 += __shfl_xor_sync(0xffffffffu, lsum1, 1);
    lsum1 += __shfl_xor_sync(0xffffffffu, lsum1, 2);
    float inv0 = 1.f / lsum0, inv1 = 1.f / lsum1;
    float* o0 = &out[(size_t)(b * S_ + row0 + wr + g) * D_ + h * 64];
    float* o1 = o0 + 8 * D_;
    #pragma unroll
    for (int nt = 0; nt < 8; nt++) {
        float2 w0; w0.x = oacc[nt][0] * inv0; w0.y = oacc[nt][1] * inv0;
        float2 w1; w1.x = oacc[nt][2] * inv1; w1.y = oacc[nt][3] * inv1;
        *(float2*)&o0[nt * 8 + tg * 2] = w0;
        *(float2*)&o1[nt * 8 + tg * 2] = w1;
    }
}

// ---------------------------------------------------------------------------
extern "C" void kernel_launch(void* const* d_in, const int* in_sizes, int n_in,
                              void* d_out, int out_size)
{
    const float* hidden = (const float*)d_in[0];
    const float* Wq  = (const float*)d_in[1];
    const float* bq  = (const float*)d_in[2];
    const float* Wk  = (const float*)d_in[3];
    const float* bk  = (const float*)d_in[4];
    const float* Wv  = (const float*)d_in[5];
    const float* bv  = (const float*)d_in[6];
    const float* Wqg = (const float*)d_in[7];
    const float* bqg = (const float*)d_in[8];
    const float* Wkg = (const float*)d_in[9];
    const float* bkg = (const float*)d_in[10];
    const float* Wvg = (const float*)d_in[11];
    const float* bvg = (const float*)d_in[12];
    float* out = (float*)d_out;

    static cudaStream_t s2;
    static cudaEvent_t evConv, evS2;
    static int configured = 0;
    if (!configured) {
        cudaFuncSetAttribute(gemm3_kernel, cudaFuncAttributeMaxDynamicSharedMemorySize, GEMM_DYN);
        cudaFuncSetAttribute(gemm1_kernel, cudaFuncAttributeMaxDynamicSharedMemorySize, GEMM1_DYN);
        cudaFuncSetAttribute(band_mma_kernel, cudaFuncAttributeMaxDynamicSharedMemorySize, BAND_DYN);
        cudaStreamCreateWithFlags(&s2, cudaStreamNonBlocking);
        cudaEventCreateWithFlags(&evConv, cudaEventDisableTiming);
        cudaEventCreateWithFlags(&evS2, cudaEventDisableTiming);
        configured = 1;
    }

    // stream0: prepasses
    convA_kernel<<<(B_*S_*D_)/1024, 256>>>(hidden);
    convW_kernel<<<dim3(24, 24, 6), dim3(32, 8)>>>(Wq, Wk, Wv, Wkg, Wvg, Wqg);
    cudaEventRecord(evConv, 0);

    // stream2: global path (Kg, qg fp16; Vg hi/lo) + global attention
    cudaStreamWaitEvent(s2, evConv, 0);
    gemm1_kernel<<<dim3(6, 64, 2), 256, GEMM1_DYN, s2>>>(bq, bk, bkg, bqg, 3, 5);
    gemm3_kernel<<<dim3(6, 64), 256, GEMM_DYN, s2>>>(bvg, 4);
    gattn_mma_kernel<<<dim3(8, H_, B_), 256, 0, s2>>>();
    cudaEventRecord(evS2, s2);

    // stream0: band path (Q, K fp16; V hi/lo) + band attention
    gemm1_kernel<<<dim3(6, 64, 2), 256, GEMM1_DYN>>>(bq, bk, bkg, bqg, 0, 1);
    gemm3_kernel<<<dim3(6, 64), 256, GEMM_DYN>>>(bv, 2);
    band_mma_kernel<<<dim3(NC_ * 2, H_, B_), 256, BAND_DYN>>>(out);

    // join, then combine
    cudaStreamWaitEvent(0, evS2, 0);
    gattn_combine_kernel<<<B_ * H_ * G_, 64>>>(out);
}